// round 9
// baseline (speedup 1.0000x reference)
#include <cuda_runtime.h>
#include <cuda_bf16.h>
#include <cstdint>
#include <cstddef>

#define CUR   512
#define FULL  1024
#define BS    4
#define DIMM  1024
#define NH    16
#define HD    64
#define PREV  512

typedef __nv_bfloat16 bf;

// ---------------- scratch (bf16 hi/lo pairs + fp32 C2) ----------------
__device__ __align__(256) bf g_FIh[4194304], g_FIl[4194304];     // full_input
__device__ __align__(256) bf g_INh[2097152], g_INl[2097152];     // inputs
__device__ __align__(256) bf g_PEh[1048576], g_PEl[1048576];     // pos_embedding
__device__ __align__(256) bf g_Wkvh[2097152], g_Wkvl[2097152];
__device__ __align__(256) bf g_Wqh[1048576],  g_Wql[1048576];
__device__ __align__(256) bf g_Wph[1048576],  g_Wpl[1048576];
__device__ __align__(256) bf g_Wprh[1048576], g_Wprl[1048576];
__device__ __align__(256) bf g_KVh[8388608],  g_KVl[8388608];    // (4096,2048) K|V
__device__ __align__(256) bf g_Quh[2097152],  g_Qul[2097152];    // 0.125*(Q+u)
__device__ __align__(256) bf g_Qvh[2097152],  g_Qvl[2097152];    // 0.125*(Q+v)
__device__ __align__(256) bf g_Rh[1048576],   g_Rl[1048576];
__device__ __align__(256) bf g_AVh[2097152],  g_AVl[2097152];
__device__ float g_C2[(size_t)BS * NH * CUR * FULL];

// ---------------- helpers ----------------
__device__ __forceinline__ uint32_t smem_u32(const void* p) {
    return (uint32_t)__cvta_generic_to_shared(p);
}
__device__ __forceinline__ void ldsm4(uint32_t* r, uint32_t a) {
    asm volatile("ldmatrix.sync.aligned.m8n8.x4.shared.b16 {%0,%1,%2,%3}, [%4];"
        : "=r"(r[0]), "=r"(r[1]), "=r"(r[2]), "=r"(r[3]) : "r"(a));
}
__device__ __forceinline__ void ldsm4t(uint32_t* r, uint32_t a) {
    asm volatile("ldmatrix.sync.aligned.m8n8.x4.trans.shared.b16 {%0,%1,%2,%3}, [%4];"
        : "=r"(r[0]), "=r"(r[1]), "=r"(r[2]), "=r"(r[3]) : "r"(a));
}
__device__ __forceinline__ void mmabf(float* d, const uint32_t* a, const uint32_t* b) {
    asm volatile(
        "mma.sync.aligned.m16n8k16.row.col.f32.bf16.bf16.f32 "
        "{%0,%1,%2,%3},{%4,%5,%6,%7},{%8,%9},{%0,%1,%2,%3};"
        : "+f"(d[0]), "+f"(d[1]), "+f"(d[2]), "+f"(d[3])
        : "r"(a[0]), "r"(a[1]), "r"(a[2]), "r"(a[3]), "r"(b[0]), "r"(b[1]));
}
__device__ __forceinline__ void store_split(bf* ph, bf* pl, float x, float y) {
    bf hx = __float2bfloat16(x), hy = __float2bfloat16(y);
    __nv_bfloat162 H; H.x = hx; H.y = hy;
    __nv_bfloat162 L;
    L.x = __float2bfloat16(x - __bfloat162float(hx));
    L.y = __float2bfloat16(y - __bfloat162float(hy));
    *(__nv_bfloat162*)ph = H;
    *(__nv_bfloat162*)pl = L;
}
__device__ __forceinline__ void split2(float x, float y, uint32_t& h, uint32_t& l) {
    bf hx = __float2bfloat16(x), hy = __float2bfloat16(y);
    __nv_bfloat162 H; H.x = hx; H.y = hy;
    __nv_bfloat162 L;
    L.x = __float2bfloat16(x - __bfloat162float(hx));
    L.y = __float2bfloat16(y - __bfloat162float(hy));
    h = *reinterpret_cast<uint32_t*>(&H);
    l = *reinterpret_cast<uint32_t*>(&L);
}
#define CPA(dst, src) \
    asm volatile("cp.async.cg.shared.global [%0], [%1], 16;" :: "r"(dst), "l"(src))
#define CPC() asm volatile("cp.async.commit_group;" ::: "memory")
#define CPW(n) asm volatile("cp.async.wait_group %0;" :: "n"(n) : "memory")
__device__ __forceinline__ void cpw_rem(int rem) {
    if (rem >= 2) CPW(2);
    else if (rem == 1) CPW(1);
    else CPW(0);
}

// ---------------- merged converter ----------------
struct CT {
    const float* s[7];
    bf* h[7];
    bf* l[7];
    int end[7];
};
__global__ __launch_bounds__(256)
void cvt_mega(CT c)
{
    const int bid = blockIdx.x;
    int ti = 0;
    #pragma unroll
    for (int k = 0; k < 6; k++) ti += (bid >= c.end[k]) ? 1 : 0;
    const int base = ti ? c.end[ti - 1] : 0;
    const int i = ((bid - base) * 256 + threadIdx.x) * 4;
    const float* x = c.s[ti];
    float4 v = *(const float4*)&x[i];
    store_split(&c.h[ti][i],     &c.l[ti][i],     v.x, v.y);
    store_split(&c.h[ti][i + 2], &c.l[ti][i + 2], v.z, v.w);
}

// ---------------------------------------------------------------------------
// Mega GEMM (unchanged from R8): up to 3 tasks, 128x128 tile, BK=32, 256 thr,
// 4-stage cp.async, 3-term hi/lo.
// ---------------------------------------------------------------------------
struct GTask {
    const bf *Ah, *Al, *Bh, *Bl;
    const float *bias, *uvec, *vvec;
    float* Cf;
    bf *Xh, *Xl, *Yh, *Yl;
    int N, K, nbx, mode;
};
struct GT3 { GTask t[3]; int end0, end1; };

#define GSTAGE 37888
__global__ __launch_bounds__(256)
void gemm_mega(GT3 ts)
{
    extern __shared__ char dsm[];
    const int bid = blockIdx.x;
    const int ti = (bid >= ts.end0 ? 1 : 0) + (bid >= ts.end1 ? 1 : 0);
    const GTask T = ts.t[ti];
    const int base = (ti == 0) ? 0 : (ti == 1 ? ts.end0 : ts.end1);
    const int local = bid - base;
    const int by = local / T.nbx, bx = local - by * T.nbx;

    const int tid = threadIdx.x, lane = tid & 31, wid = tid >> 5;
    const int wm = wid >> 1, wn = wid & 1;
    const int m0 = by * 128, n0 = bx * 128;
    const int N = T.N, K = T.K;

    const int lam = tid >> 1;
    const int lac = (tid & 1) * 16;
    const int lbk = tid >> 3;
    const int lbn = (tid & 7) * 16;

    const bf* gAh = T.Ah + (size_t)(m0 + lam) * K + lac;
    const bf* gAl = T.Al + (size_t)(m0 + lam) * K + lac;
    const bf* gBh = T.Bh + (size_t)lbk * N + n0 + lbn;
    const bf* gBl = T.Bl + (size_t)lbk * N + n0 + lbn;

    const uint32_t dA0 = smem_u32(dsm) + lam * 80 + (tid & 1) * 32;
    const uint32_t dB0 = smem_u32(dsm) + 20480 + lbk * 272 + (tid & 7) * 32;

    const int nc = K / 32;

    auto issue = [&](int t) {
        const int s = t & 3;
        const uint32_t da = dA0 + s * GSTAGE;
        const uint32_t db = dB0 + s * GSTAGE;
        const bf* ah = gAh + t * 32;
        const bf* al = gAl + t * 32;
        const bf* bh = gBh + (size_t)t * 32 * N;
        const bf* bl = gBl + (size_t)t * 32 * N;
        CPA(da,          ah);     CPA(da + 16,          ah + 8);
        CPA(da + 10240,  al);     CPA(da + 10240 + 16,  al + 8);
        CPA(db,          bh);     CPA(db + 16,          bh + 8);
        CPA(db + 8704,   bl);     CPA(db + 8704 + 16,   bl + 8);
        CPC();
    };

    issue(0); issue(1); issue(2);

    float acc[2][8][4] = {};

    for (int t = 0; t < nc; t++) {
        cpw_rem(nc - 1 - t);
        __syncthreads();
        if (t + 3 < nc) issue(t + 3);

        char* st = dsm + (t & 3) * GSTAGE;
        bf* sAh = (bf*)st;
        bf* sAl = (bf*)(st + 10240);
        bf* sBh = (bf*)(st + 20480);
        bf* sBl = (bf*)(st + 29184);

        #pragma unroll
        for (int s = 0; s < 2; s++) {
            const int ks = s * 16;
            uint32_t ahf[2][4], alf[2][4], bhf[8][2], blf[8][2];
            #pragma unroll
            for (int f = 0; f < 2; f++) {
                int row = wm * 32 + f * 16 + (lane & 15);
                int kc  = ks + ((lane & 16) >> 1);
                ldsm4(ahf[f], smem_u32(&sAh[row * 40 + kc]));
                ldsm4(alf[f], smem_u32(&sAl[row * 40 + kc]));
            }
            #pragma unroll
            for (int g4 = 0; g4 < 4; g4++) {
                int krow = ks + (lane & 15);
                int ncc  = wn * 64 + g4 * 16 + ((lane & 16) >> 1);
                uint32_t tt[4];
                ldsm4t(tt, smem_u32(&sBh[krow * 136 + ncc]));
                bhf[2*g4][0] = tt[0]; bhf[2*g4][1] = tt[1];
                bhf[2*g4+1][0] = tt[2]; bhf[2*g4+1][1] = tt[3];
                ldsm4t(tt, smem_u32(&sBl[krow * 136 + ncc]));
                blf[2*g4][0] = tt[0]; blf[2*g4][1] = tt[1];
                blf[2*g4+1][0] = tt[2]; blf[2*g4+1][1] = tt[3];
            }
            #pragma unroll
            for (int f = 0; f < 2; f++)
                #pragma unroll
                for (int g = 0; g < 8; g++) {
                    mmabf(acc[f][g], ahf[f], bhf[g]);
                    mmabf(acc[f][g], ahf[f], blf[g]);
                    mmabf(acc[f][g], alf[f], bhf[g]);
                }
        }
    }

    const int r = lane >> 2, c2 = (lane & 3) * 2;
    #pragma unroll
    for (int f = 0; f < 2; f++) {
        int row0 = m0 + wm * 32 + f * 16 + r;
        #pragma unroll
        for (int g = 0; g < 8; g++) {
            int col = n0 + wn * 64 + g * 8 + c2;
            float2 b2 = *(const float2*)&T.bias[col];
            float v00 = acc[f][g][0] + b2.x, v01 = acc[f][g][1] + b2.y;
            float v10 = acc[f][g][2] + b2.x, v11 = acc[f][g][3] + b2.y;
            size_t i0o = (size_t)row0 * N + col;
            size_t i1o = (size_t)(row0 + 8) * N + col;
            if (T.mode == 0) {
                *(float2*)&T.Cf[i0o] = make_float2(v00, v01);
                *(float2*)&T.Cf[i1o] = make_float2(v10, v11);
            } else if (T.mode == 1) {
                store_split(&T.Xh[i0o], &T.Xl[i0o], v00, v01);
                store_split(&T.Xh[i1o], &T.Xl[i1o], v10, v11);
            } else {
                float2 uu = *(const float2*)&T.uvec[col];
                float2 vv = *(const float2*)&T.vvec[col];
                store_split(&T.Xh[i0o], &T.Xl[i0o], 0.125f*(v00 + uu.x), 0.125f*(v01 + uu.y));
                store_split(&T.Xh[i1o], &T.Xl[i1o], 0.125f*(v10 + uu.x), 0.125f*(v11 + uu.y));
                store_split(&T.Yh[i0o], &T.Yl[i0o], 0.125f*(v00 + vv.x), 0.125f*(v01 + vv.y));
                store_split(&T.Yh[i1o], &T.Yl[i1o], 0.125f*(v10 + vv.x), 0.125f*(v11 + vv.y));
            }
        }
    }
}

// ---------------------------------------------------------------------------
// Position scores (unchanged): C2[bh,i,k] = Qv . R (pre-scaled).
// ---------------------------------------------------------------------------
__global__ __launch_bounds__(128)
void pos_scores_bb(const bf* __restrict__ Qvh, const bf* __restrict__ Qvl,
                   const bf* __restrict__ Rh, const bf* __restrict__ Rl,
                   float* __restrict__ C2)
{
    const int bh = blockIdx.z, b = bh >> 4, h = bh & 15;
    const int i0 = blockIdx.y * 64, n0 = blockIdx.x * 64;
    if (n0 + i0 < 385) return;

    __shared__ bf sQh[64][72], sQl[64][72], sRh[64][72], sRl[64][72];

    const int tid = threadIdx.x, lane = tid & 31, wid = tid >> 5;
    const int wm = wid >> 1, wn = wid & 1;

    {
        const int row = tid >> 1, cb = (tid & 1) * 32;
        const size_t qoff = (size_t)((i0 + row) * BS + b) * DIMM + h * HD + cb;
        const size_t roff = (size_t)(n0 + row) * DIMM + h * HD + cb;
        #pragma unroll
        for (int q = 0; q < 4; q++) {
            *(uint4*)&sQh[row][cb + q * 8] = *(const uint4*)&Qvh[qoff + q * 8];
            *(uint4*)&sQl[row][cb + q * 8] = *(const uint4*)&Qvl[qoff + q * 8];
            *(uint4*)&sRh[row][cb + q * 8] = *(const uint4*)&Rh[roff + q * 8];
            *(uint4*)&sRl[row][cb + q * 8] = *(const uint4*)&Rl[roff + q * 8];
        }
    }
    __syncthreads();

    float acc[2][4][4] = {};
    #pragma unroll
    for (int s = 0; s < 4; s++) {
        const int ks = s * 16;
        uint32_t ah[2][4], al[2][4], bh2[4][2], bl2[4][2];
        #pragma unroll
        for (int f = 0; f < 2; f++) {
            int row = wm * 32 + f * 16 + (lane & 15);
            int kc  = ks + ((lane & 16) >> 1);
            ldsm4(ah[f], smem_u32(&sQh[row][kc]));
            ldsm4(al[f], smem_u32(&sQl[row][kc]));
        }
        #pragma unroll
        for (int g4 = 0; g4 < 2; g4++) {
            int nrow = wn * 32 + g4 * 16 + (lane & 15);
            int kc   = ks + ((lane & 16) >> 1);
            uint32_t t[4];
            ldsm4(t, smem_u32(&sRh[nrow][kc]));
            bh2[2*g4][0] = t[0]; bh2[2*g4+1][0] = t[1];
            bh2[2*g4][1] = t[2]; bh2[2*g4+1][1] = t[3];
            ldsm4(t, smem_u32(&sRl[nrow][kc]));
            bl2[2*g4][0] = t[0]; bl2[2*g4+1][0] = t[1];
            bl2[2*g4][1] = t[2]; bl2[2*g4+1][1] = t[3];
        }
        #pragma unroll
        for (int f = 0; f < 2; f++)
            #pragma unroll
            for (int g = 0; g < 4; g++) {
                mmabf(acc[f][g], ah[f], bh2[g]);
                mmabf(acc[f][g], ah[f], bl2[g]);
                mmabf(acc[f][g], al[f], bh2[g]);
            }
    }

    const int r = lane >> 2, c2 = (lane & 3) * 2;
    float* out = C2 + (size_t)bh * CUR * FULL;
    #pragma unroll
    for (int f = 0; f < 2; f++) {
        int row0 = i0 + wm * 32 + f * 16 + r;
        #pragma unroll
        for (int g = 0; g < 4; g++) {
            int col = n0 + wn * 32 + g * 8 + c2;
            *(float2*)&out[(size_t)row0 * FULL + col]       = make_float2(acc[f][g][0], acc[f][g][1]);
            *(float2*)&out[(size_t)(row0 + 8) * FULL + col] = make_float2(acc[f][g][2], acc[f][g][3]);
        }
    }
}

// ---------------------------------------------------------------------------
// Fused attention: 128 query rows / block, 256 threads (8 warps, 16 rows
// each). 2-stage cp.async K/V pipeline; per-warp band masking.
// ---------------------------------------------------------------------------
#define ASTAGE 36864
__global__ __launch_bounds__(256)
void attn_ca(const bf* __restrict__ Quh, const bf* __restrict__ Qul,
             const bf* __restrict__ KVh, const bf* __restrict__ KVl,
             const float* __restrict__ C2,
             bf* __restrict__ AVh, bf* __restrict__ AVl)
{
    extern __shared__ char dsm[];
    __shared__ bf Qh_s[128][72], Ql_s[128][72];

    const int bh = blockIdx.y, b = bh >> 4, h = bh & 15;
    const int i0 = blockIdx.x * 128;

    const int tid = threadIdx.x, lane = tid & 31, w = tid >> 5;
    const int r = lane >> 2, cq = lane & 3;

    const int jtiles = i0 / 64 + 10;

    // K/V tile loader: 64 rows x 64 cols x 4 arrays, 256 threads.
    const int kii = tid >> 2, kcb = (tid & 3) * 16;
    auto issue_kv = [&](int jt) {
        char* st = dsm + (jt & 1) * ASTAGE;
        const size_t koff = (size_t)((jt * 64 + kii) * BS + b) * (2 * DIMM) + h * HD + kcb;
        const char* gKh = (const char*)(KVh + koff);
        const char* gKl = (const char*)(KVl + koff);
        const char* gVh = (const char*)(KVh + koff + DIMM);
        const char* gVl = (const char*)(KVl + koff + DIMM);
        const uint32_t d = smem_u32(st) + kii * 144 + (tid & 3) * 32;
        #pragma unroll
        for (int c = 0; c < 2; c++) {
            CPA(d +         c * 16, gKh + c * 16);
            CPA(d + 9216  + c * 16, gKl + c * 16);
            CPA(d + 18432 + c * 16, gVh + c * 16);
            CPA(d + 27648 + c * 16, gVl + c * 16);
        }
        CPC();
    };

    issue_kv(0);
    {
        const int qi = tid >> 1, qc = (tid & 1) * 32;
        const size_t qoff = (size_t)((i0 + qi) * BS + b) * DIMM + h * HD + qc;
        #pragma unroll
        for (int q = 0; q < 4; q++) {
            *(uint4*)&Qh_s[qi][qc + q * 8] = *(const uint4*)&Quh[qoff + q * 8];
            *(uint4*)&Ql_s[qi][qc + q * 8] = *(const uint4*)&Qul[qoff + q * 8];
        }
    }
    __syncthreads();

    uint32_t qh[4][4], ql[4][4];
    #pragma unroll
    for (int s = 0; s < 4; s++) {
        int rowi = w * 16 + (lane & 15);
        int kc  = s * 16 + ((lane & 16) >> 1);
        ldsm4(qh[s], smem_u32(&Qh_s[rowi][kc]));
        ldsm4(ql[s], smem_u32(&Ql_s[rowi][kc]));
    }

    float oacc[8][4] = {};
    float m0 = -1e30f, m1 = -1e30f, l0 = 0.f, l1 = 0.f;

    const int irow0 = i0 + w * 16 + r;
    const float* c2row0 = C2 + ((size_t)bh * CUR + irow0) * FULL;
    const float* c2row1 = c2row0 + (size_t)8 * FULL;

    for (int jt = 0; jt < jtiles; jt++) {
        const int j0 = jt * 64;
        CPW(0);
        __syncthreads();
        if (jt + 1 < jtiles) issue_kv(jt + 1);

        char* st = dsm + (jt & 1) * ASTAGE;
        bf* Kh_s = (bf*)st;
        bf* Kl_s = (bf*)(st + 9216);
        bf* Vh_s = (bf*)(st + 18432);
        bf* Vl_s = (bf*)(st + 27648);

        float sacc[8][4] = {};
        #pragma unroll
        for (int s = 0; s < 4; s++) {
            const int ks = s * 16;
            uint32_t bhf[8][2], blf[8][2];
            #pragma unroll
            for (int g4 = 0; g4 < 4; g4++) {
                int nrow = g4 * 16 + (lane & 15);
                int kc   = ks + ((lane & 16) >> 1);
                uint32_t t[4];
                ldsm4(t, smem_u32(&Kh_s[nrow * 72 + kc]));
                bhf[2*g4][0] = t[0]; bhf[2*g4+1][0] = t[1];
                bhf[2*g4][1] = t[2]; bhf[2*g4+1][1] = t[3];
                ldsm4(t, smem_u32(&Kl_s[nrow * 72 + kc]));
                blf[2*g4][0] = t[0]; blf[2*g4+1][0] = t[1];
                blf[2*g4][1] = t[2]; blf[2*g4+1][1] = t[3];
            }
            #pragma unroll
            for (int g = 0; g < 8; g++) {
                mmabf(sacc[g], qh[s], bhf[g]);
                mmabf(sacc[g], qh[s], blf[g]);
                mmabf(sacc[g], ql[s], bhf[g]);
            }
        }

        // Per-warp masking: rows irow0/irow0+8; valid iff k ∈ [0, 1023].
        const bool need_mask = (j0 + 63 > irow0 + PREV);
        #pragma unroll
        for (int g = 0; g < 8; g++) {
            int jg  = j0 + g * 8 + 2 * cq;
            int k00 = jg - irow0 + 511;
            int k10 = k00 - 8;
            if (!need_mask) {
                sacc[g][0] += c2row0[k00];
                sacc[g][1] += c2row0[k00 + 1];
                sacc[g][2] += c2row1[k10];
                sacc[g][3] += c2row1[k10 + 1];
            } else {
                sacc[g][0] = (k00     <= 1023) ? sacc[g][0] + c2row0[k00]     : -1e30f;
                sacc[g][1] = (k00 + 1 <= 1023) ? sacc[g][1] + c2row0[k00 + 1] : -1e30f;
                sacc[g][2] = (k10     <= 1023) ? sacc[g][2] + c2row1[k10]     : -1e30f;
                sacc[g][3] = (k10 + 1 <= 1023) ? sacc[g][3] + c2row1[k10 + 1] : -1e30f;
            }
        }

        float mx0 = -1e30f, mx1 = -1e30f;
        #pragma unroll
        for (int g = 0; g < 8; g++) {
            mx0 = fmaxf(mx0, fmaxf(sacc[g][0], sacc[g][1]));
            mx1 = fmaxf(mx1, fmaxf(sacc[g][2], sacc[g][3]));
        }
        mx0 = fmaxf(mx0, __shfl_xor_sync(0xffffffffu, mx0, 1));
        mx0 = fmaxf(mx0, __shfl_xor_sync(0xffffffffu, mx0, 2));
        mx1 = fmaxf(mx1, __shfl_xor_sync(0xffffffffu, mx1, 1));
        mx1 = fmaxf(mx1, __shfl_xor_sync(0xffffffffu, mx1, 2));

        float mn0 = fmaxf(m0, mx0), mn1 = fmaxf(m1, mx1);
        float a0 = __expf(m0 - mn0), a1 = __expf(m1 - mn1);
        m0 = mn0; m1 = mn1;
        l0 *= a0; l1 *= a1;
        #pragma unroll
        for (int g = 0; g < 8; g++) {
            oacc[g][0] *= a0; oacc[g][1] *= a0;
            oacc[g][2] *= a1; oacc[g][3] *= a1;
        }

        float p[8][4];
        #pragma unroll
        for (int g = 0; g < 8; g++) {
            p[g][0] = __expf(sacc[g][0] - m0);
            p[g][1] = __expf(sacc[g][1] - m0);
            p[g][2] = __expf(sacc[g][2] - m1);
            p[g][3] = __expf(sacc[g][3] - m1);
            l0 += p[g][0] + p[g][1];
            l1 += p[g][2] + p[g][3];
        }

        #pragma unroll
        for (int t4 = 0; t4 < 4; t4++) {
            uint32_t pah[4], pal[4];
            split2(p[2*t4][0],   p[2*t4][1],   pah[0], pal[0]);
            split2(p[2*t4][2],   p[2*t4][3],   pah[1], pal[1]);
            split2(p[2*t4+1][0], p[2*t4+1][1], pah[2], pal[2]);
            split2(p[2*t4+1][2], p[2*t4+1][3], pah[3], pal[3]);

            uint32_t vhf[8][2], vlf[8][2];
            #pragma unroll
            for (int g4 = 0; g4 < 4; g4++) {
                int krow = t4 * 16 + (lane & 15);
                int ncc  = g4 * 16 + ((lane & 16) >> 1);
                uint32_t t[4];
                ldsm4t(t, smem_u32(&Vh_s[krow * 72 + ncc]));
                vhf[2*g4][0] = t[0]; vhf[2*g4][1] = t[1];
                vhf[2*g4+1][0] = t[2]; vhf[2*g4+1][1] = t[3];
                ldsm4t(t, smem_u32(&Vl_s[krow * 72 + ncc]));
                vlf[2*g4][0] = t[0]; vlf[2*g4][1] = t[1];
                vlf[2*g4+1][0] = t[2]; vlf[2*g4+1][1] = t[3];
            }
            #pragma unroll
            for (int g = 0; g < 8; g++) {
                mmabf(oacc[g], pah, vhf[g]);
                mmabf(oacc[g], pah, vlf[g]);
                mmabf(oacc[g], pal, vhf[g]);
            }
        }
    }

    l0 += __shfl_xor_sync(0xffffffffu, l0, 1);
    l0 += __shfl_xor_sync(0xffffffffu, l0, 2);
    l1 += __shfl_xor_sync(0xffffffffu, l1, 1);
    l1 += __shfl_xor_sync(0xffffffffu, l1, 2);
    const float inv0 = 1.f / l0, inv1 = 1.f / l1;

    const size_t o0 = (size_t)(irow0 * BS + b) * DIMM + h * HD;
    const size_t o1 = (size_t)((irow0 + 8) * BS + b) * DIMM + h * HD;
    #pragma unroll
    for (int g = 0; g < 8; g++) {
        int col = g * 8 + 2 * cq;
        store_split(&AVh[o0 + col], &AVl[o0 + col], oacc[g][0] * inv0, oacc[g][1] * inv0);
        store_split(&AVh[o1 + col], &AVl[o1 + col], oacc[g][2] * inv1, oacc[g][3] * inv1);
    }
}

// ---------------------------------------------------------------------------
// Launch
// ---------------------------------------------------------------------------
extern "C" void kernel_launch(void* const* d_in, const int* in_sizes, int n_in,
                              void* d_out, int out_size)
{
    const float* inputs  = (const float*)d_in[0];
    const float* pos_emb = (const float*)d_in[1];
    const float* full_in = (const float*)d_in[2];
    const float* u       = (const float*)d_in[3];
    const float* v       = (const float*)d_in[4];
    const float* W_kv    = (const float*)d_in[5];
    const float* b_kv    = (const float*)d_in[6];
    const float* W_q     = (const float*)d_in[7];
    const float* b_q     = (const float*)d_in[8];
    const float* W_pos   = (const float*)d_in[9];
    const float* b_pos   = (const float*)d_in[10];
    const float* W_proj  = (const float*)d_in[11];
    const float* b_proj  = (const float*)d_in[12];
    float* out = (float*)d_out;

    bf *FIh, *FIl, *INh, *INl, *PEh, *PEl, *Wkvh, *Wkvl, *Wqh, *Wql,
       *Wph, *Wpl, *Wprh, *Wprl, *KVh, *KVl, *Quh, *Qul, *Qvh, *Qvl,
       *Rh, *Rl, *AVh, *AVl;
    float *C2;
    cudaGetSymbolAddress((void**)&FIh, g_FIh);   cudaGetSymbolAddress((void**)&FIl, g_FIl);
    cudaGetSymbolAddress((void**)&INh, g_INh);   cudaGetSymbolAddress((void**)&INl, g_INl);
    cudaGetSymbolAddress((void**)&PEh, g_PEh);   cudaGetSymbolAddress((void**)&PEl, g_PEl);
    cudaGetSymbolAddress((void**)&Wkvh, g_Wkvh); cudaGetSymbolAddress((void**)&Wkvl, g_Wkvl);
    cudaGetSymbolAddress((void**)&Wqh, g_Wqh);   cudaGetSymbolAddress((void**)&Wql, g_Wql);
    cudaGetSymbolAddress((void**)&Wph, g_Wph);   cudaGetSymbolAddress((void**)&Wpl, g_Wpl);
    cudaGetSymbolAddress((void**)&Wprh, g_Wprh); cudaGetSymbolAddress((void**)&Wprl, g_Wprl);
    cudaGetSymbolAddress((void**)&KVh, g_KVh);   cudaGetSymbolAddress((void**)&KVl, g_KVl);
    cudaGetSymbolAddress((void**)&Quh, g_Quh);   cudaGetSymbolAddress((void**)&Qul, g_Qul);
    cudaGetSymbolAddress((void**)&Qvh, g_Qvh);   cudaGetSymbolAddress((void**)&Qvl, g_Qvl);
    cudaGetSymbolAddress((void**)&Rh, g_Rh);     cudaGetSymbolAddress((void**)&Rl, g_Rl);
    cudaGetSymbolAddress((void**)&AVh, g_AVh);   cudaGetSymbolAddress((void**)&AVl, g_AVl);
    cudaGetSymbolAddress((void**)&C2, g_C2);

    const int GSM = 4 * GSTAGE;     // 151552
    const int ASM = 2 * ASTAGE;     // 73728
    cudaFuncSetAttribute(gemm_mega, cudaFuncAttributeMaxDynamicSharedMemorySize, GSM);
    cudaFuncSetAttribute(attn_ca,   cudaFuncAttributeMaxDynamicSharedMemorySize, ASM);

    // 1. All conversions in one grid
    CT ct;
    ct.s[0] = full_in; ct.h[0] = FIh;  ct.l[0] = FIl;
    ct.s[1] = inputs;  ct.h[1] = INh;  ct.l[1] = INl;
    ct.s[2] = pos_emb; ct.h[2] = PEh;  ct.l[2] = PEl;
    ct.s[3] = W_kv;    ct.h[3] = Wkvh; ct.l[3] = Wkvl;
    ct.s[4] = W_q;     ct.h[4] = Wqh;  ct.l[4] = Wql;
    ct.s[5] = W_pos;   ct.h[5] = Wph;  ct.l[5] = Wpl;
    ct.s[6] = W_proj;  ct.h[6] = Wprh; ct.l[6] = Wprl;
    ct.end[0] = 4096;  ct.end[1] = 6144;  ct.end[2] = 7168;
    ct.end[3] = 9216;  ct.end[4] = 10240; ct.end[5] = 11264; ct.end[6] = 12288;
    cvt_mega<<<12288, 256>>>(ct);

    // 2. Mega GEMM {KV, Q(+u/v, x0.125), R}
    GT3 ts;
    ts.t[0] = { FIh, FIl, Wkvh, Wkvl, b_kv, nullptr, nullptr,
                nullptr, KVh, KVl, nullptr, nullptr, 2048, 1024, 16, 1 };
    ts.t[1] = { INh, INl, Wqh, Wql, b_q, u, v,
                nullptr, Quh, Qul, Qvh, Qvl, 1024, 1024, 8, 2 };
    ts.t[2] = { PEh, PEl, Wph, Wpl, b_pos, nullptr, nullptr,
                nullptr, Rh, Rl, nullptr, nullptr, 1024, 1024, 8, 1 };
    ts.end0 = 512; ts.end1 = 640;
    gemm_mega<<<704, 256, GSM>>>(ts);

    // 3. Position scores (pre-scaled)
    pos_scores_bb<<<dim3(FULL / 64, CUR / 64, BS * NH), 128>>>(Qvh, Qvl, Rh, Rl, C2);

    // 4. Fused attention (128 rows/block)
    attn_ca<<<dim3(CUR / 128, BS * NH), 256, ASM>>>(Quh, Qul, KVh, KVl, C2, AVh, AVl);

    // 5. out = AV @ W_proj + b_proj (fp32)
    GT3 tp;
    tp.t[0] = { AVh, AVl, Wprh, Wprl, b_proj, nullptr, nullptr,
                out, nullptr, nullptr, nullptr, nullptr, 1024, 1024, 8, 0 };
    tp.t[1] = tp.t[0]; tp.t[2] = tp.t[0];
    tp.end0 = 128; tp.end1 = 128;
    gemm_mega<<<128, 256, GSM>>>(tp);
}

// round 10
// speedup vs baseline: 1.1278x; 1.1278x over previous
#include <cuda_runtime.h>
#include <cuda_bf16.h>
#include <cstdint>
#include <cstddef>

#define CUR   512
#define FULL  1024
#define BS    4
#define DIMM  1024
#define NH    16
#define HD    64
#define PREV  512

typedef __nv_bfloat16 bf;

// ---------------- scratch (bf16 hi/lo pairs + fp32 C2) ----------------
__device__ __align__(256) bf g_FIh[4194304], g_FIl[4194304];     // full_input
__device__ __align__(256) bf g_INh[2097152], g_INl[2097152];     // inputs
__device__ __align__(256) bf g_PEh[1048576], g_PEl[1048576];     // pos_embedding
__device__ __align__(256) bf g_Wkvh[2097152], g_Wkvl[2097152];
__device__ __align__(256) bf g_Wqh[1048576],  g_Wql[1048576];
__device__ __align__(256) bf g_Wph[1048576],  g_Wpl[1048576];
__device__ __align__(256) bf g_Wprh[1048576], g_Wprl[1048576];
__device__ __align__(256) bf g_KVh[8388608],  g_KVl[8388608];    // (4096,2048) K|V
__device__ __align__(256) bf g_Quh[2097152],  g_Qul[2097152];    // 0.125*(Q+u)
__device__ __align__(256) bf g_Qvh[2097152],  g_Qvl[2097152];    // 0.125*(Q+v)
__device__ __align__(256) bf g_Rh[1048576],   g_Rl[1048576];
__device__ __align__(256) bf g_AVh[2097152],  g_AVl[2097152];
__device__ float g_C2[(size_t)BS * NH * CUR * FULL];

// ---------------- helpers ----------------
__device__ __forceinline__ uint32_t smem_u32(const void* p) {
    return (uint32_t)__cvta_generic_to_shared(p);
}
__device__ __forceinline__ void ldsm4(uint32_t* r, uint32_t a) {
    asm volatile("ldmatrix.sync.aligned.m8n8.x4.shared.b16 {%0,%1,%2,%3}, [%4];"
        : "=r"(r[0]), "=r"(r[1]), "=r"(r[2]), "=r"(r[3]) : "r"(a));
}
__device__ __forceinline__ void ldsm4t(uint32_t* r, uint32_t a) {
    asm volatile("ldmatrix.sync.aligned.m8n8.x4.trans.shared.b16 {%0,%1,%2,%3}, [%4];"
        : "=r"(r[0]), "=r"(r[1]), "=r"(r[2]), "=r"(r[3]) : "r"(a));
}
__device__ __forceinline__ void mmabf(float* d, const uint32_t* a, const uint32_t* b) {
    asm volatile(
        "mma.sync.aligned.m16n8k16.row.col.f32.bf16.bf16.f32 "
        "{%0,%1,%2,%3},{%4,%5,%6,%7},{%8,%9},{%0,%1,%2,%3};"
        : "+f"(d[0]), "+f"(d[1]), "+f"(d[2]), "+f"(d[3])
        : "r"(a[0]), "r"(a[1]), "r"(a[2]), "r"(a[3]), "r"(b[0]), "r"(b[1]));
}
__device__ __forceinline__ void store_split(bf* ph, bf* pl, float x, float y) {
    bf hx = __float2bfloat16(x), hy = __float2bfloat16(y);
    __nv_bfloat162 H; H.x = hx; H.y = hy;
    __nv_bfloat162 L;
    L.x = __float2bfloat16(x - __bfloat162float(hx));
    L.y = __float2bfloat16(y - __bfloat162float(hy));
    *(__nv_bfloat162*)ph = H;
    *(__nv_bfloat162*)pl = L;
}
__device__ __forceinline__ void split2(float x, float y, uint32_t& h, uint32_t& l) {
    bf hx = __float2bfloat16(x), hy = __float2bfloat16(y);
    __nv_bfloat162 H; H.x = hx; H.y = hy;
    __nv_bfloat162 L;
    L.x = __float2bfloat16(x - __bfloat162float(hx));
    L.y = __float2bfloat16(y - __bfloat162float(hy));
    h = *reinterpret_cast<uint32_t*>(&H);
    l = *reinterpret_cast<uint32_t*>(&L);
}
#define CPA(dst, src) \
    asm volatile("cp.async.cg.shared.global [%0], [%1], 16;" :: "r"(dst), "l"(src))
#define CPC() asm volatile("cp.async.commit_group;" ::: "memory")
#define CPW(n) asm volatile("cp.async.wait_group %0;" :: "n"(n) : "memory")
__device__ __forceinline__ void cpw_rem(int rem) {
    if (rem >= 2) CPW(2);
    else if (rem == 1) CPW(1);
    else CPW(0);
}

// ---------------- merged converter ----------------
struct CT {
    const float* s[7];
    bf* h[7];
    bf* l[7];
    int end[7];
};
__global__ __launch_bounds__(256)
void cvt_mega(CT c)
{
    const int bid = blockIdx.x;
    int ti = 0;
    #pragma unroll
    for (int k = 0; k < 6; k++) ti += (bid >= c.end[k]) ? 1 : 0;
    const int base = ti ? c.end[ti - 1] : 0;
    const int i = ((bid - base) * 256 + threadIdx.x) * 4;
    const float* x = c.s[ti];
    float4 v = *(const float4*)&x[i];
    store_split(&c.h[ti][i],     &c.l[ti][i],     v.x, v.y);
    store_split(&c.h[ti][i + 2], &c.l[ti][i + 2], v.z, v.w);
}

// ---------------------------------------------------------------------------
// Mega GEMM (unchanged): up to 3 tasks, 128x128 tile, BK=32, 256 thr,
// 4-stage cp.async, 3-term hi/lo.
// ---------------------------------------------------------------------------
struct GTask {
    const bf *Ah, *Al, *Bh, *Bl;
    const float *bias, *uvec, *vvec;
    float* Cf;
    bf *Xh, *Xl, *Yh, *Yl;
    int N, K, nbx, mode;
};
struct GT3 { GTask t[3]; int end0, end1; };

#define GSTAGE 37888
__global__ __launch_bounds__(256)
void gemm_mega(GT3 ts)
{
    extern __shared__ char dsm[];
    const int bid = blockIdx.x;
    const int ti = (bid >= ts.end0 ? 1 : 0) + (bid >= ts.end1 ? 1 : 0);
    const GTask T = ts.t[ti];
    const int base = (ti == 0) ? 0 : (ti == 1 ? ts.end0 : ts.end1);
    const int local = bid - base;
    const int by = local / T.nbx, bx = local - by * T.nbx;

    const int tid = threadIdx.x, lane = tid & 31, wid = tid >> 5;
    const int wm = wid >> 1, wn = wid & 1;
    const int m0 = by * 128, n0 = bx * 128;
    const int N = T.N, K = T.K;

    const int lam = tid >> 1;
    const int lac = (tid & 1) * 16;
    const int lbk = tid >> 3;
    const int lbn = (tid & 7) * 16;

    const bf* gAh = T.Ah + (size_t)(m0 + lam) * K + lac;
    const bf* gAl = T.Al + (size_t)(m0 + lam) * K + lac;
    const bf* gBh = T.Bh + (size_t)lbk * N + n0 + lbn;
    const bf* gBl = T.Bl + (size_t)lbk * N + n0 + lbn;

    const uint32_t dA0 = smem_u32(dsm) + lam * 80 + (tid & 1) * 32;
    const uint32_t dB0 = smem_u32(dsm) + 20480 + lbk * 272 + (tid & 7) * 32;

    const int nc = K / 32;

    auto issue = [&](int t) {
        const int s = t & 3;
        const uint32_t da = dA0 + s * GSTAGE;
        const uint32_t db = dB0 + s * GSTAGE;
        const bf* ah = gAh + t * 32;
        const bf* al = gAl + t * 32;
        const bf* bh = gBh + (size_t)t * 32 * N;
        const bf* bl = gBl + (size_t)t * 32 * N;
        CPA(da,          ah);     CPA(da + 16,          ah + 8);
        CPA(da + 10240,  al);     CPA(da + 10240 + 16,  al + 8);
        CPA(db,          bh);     CPA(db + 16,          bh + 8);
        CPA(db + 8704,   bl);     CPA(db + 8704 + 16,   bl + 8);
        CPC();
    };

    issue(0); issue(1); issue(2);

    float acc[2][8][4] = {};

    for (int t = 0; t < nc; t++) {
        cpw_rem(nc - 1 - t);
        __syncthreads();
        if (t + 3 < nc) issue(t + 3);

        char* st = dsm + (t & 3) * GSTAGE;
        bf* sAh = (bf*)st;
        bf* sAl = (bf*)(st + 10240);
        bf* sBh = (bf*)(st + 20480);
        bf* sBl = (bf*)(st + 29184);

        #pragma unroll
        for (int s = 0; s < 2; s++) {
            const int ks = s * 16;
            uint32_t ahf[2][4], alf[2][4], bhf[8][2], blf[8][2];
            #pragma unroll
            for (int f = 0; f < 2; f++) {
                int row = wm * 32 + f * 16 + (lane & 15);
                int kc  = ks + ((lane & 16) >> 1);
                ldsm4(ahf[f], smem_u32(&sAh[row * 40 + kc]));
                ldsm4(alf[f], smem_u32(&sAl[row * 40 + kc]));
            }
            #pragma unroll
            for (int g4 = 0; g4 < 4; g4++) {
                int krow = ks + (lane & 15);
                int ncc  = wn * 64 + g4 * 16 + ((lane & 16) >> 1);
                uint32_t tt[4];
                ldsm4t(tt, smem_u32(&sBh[krow * 136 + ncc]));
                bhf[2*g4][0] = tt[0]; bhf[2*g4][1] = tt[1];
                bhf[2*g4+1][0] = tt[2]; bhf[2*g4+1][1] = tt[3];
                ldsm4t(tt, smem_u32(&sBl[krow * 136 + ncc]));
                blf[2*g4][0] = tt[0]; blf[2*g4][1] = tt[1];
                blf[2*g4+1][0] = tt[2]; blf[2*g4+1][1] = tt[3];
            }
            #pragma unroll
            for (int f = 0; f < 2; f++)
                #pragma unroll
                for (int g = 0; g < 8; g++) {
                    mmabf(acc[f][g], ahf[f], bhf[g]);
                    mmabf(acc[f][g], ahf[f], blf[g]);
                    mmabf(acc[f][g], alf[f], bhf[g]);
                }
        }
    }

    const int r = lane >> 2, c2 = (lane & 3) * 2;
    #pragma unroll
    for (int f = 0; f < 2; f++) {
        int row0 = m0 + wm * 32 + f * 16 + r;
        #pragma unroll
        for (int g = 0; g < 8; g++) {
            int col = n0 + wn * 64 + g * 8 + c2;
            float2 b2 = *(const float2*)&T.bias[col];
            float v00 = acc[f][g][0] + b2.x, v01 = acc[f][g][1] + b2.y;
            float v10 = acc[f][g][2] + b2.x, v11 = acc[f][g][3] + b2.y;
            size_t i0o = (size_t)row0 * N + col;
            size_t i1o = (size_t)(row0 + 8) * N + col;
            if (T.mode == 0) {
                *(float2*)&T.Cf[i0o] = make_float2(v00, v01);
                *(float2*)&T.Cf[i1o] = make_float2(v10, v11);
            } else if (T.mode == 1) {
                store_split(&T.Xh[i0o], &T.Xl[i0o], v00, v01);
                store_split(&T.Xh[i1o], &T.Xl[i1o], v10, v11);
            } else {
                float2 uu = *(const float2*)&T.uvec[col];
                float2 vv = *(const float2*)&T.vvec[col];
                store_split(&T.Xh[i0o], &T.Xl[i0o], 0.125f*(v00 + uu.x), 0.125f*(v01 + uu.y));
                store_split(&T.Xh[i1o], &T.Xl[i1o], 0.125f*(v10 + uu.x), 0.125f*(v11 + uu.y));
                store_split(&T.Yh[i0o], &T.Yl[i0o], 0.125f*(v00 + vv.x), 0.125f*(v01 + vv.y));
                store_split(&T.Yh[i1o], &T.Yl[i1o], 0.125f*(v10 + vv.x), 0.125f*(v11 + vv.y));
            }
        }
    }
}

// ---------------------------------------------------------------------------
// Position scores (unchanged): C2[bh,i,k] = Qv . R (pre-scaled).
// ---------------------------------------------------------------------------
__global__ __launch_bounds__(128)
void pos_scores_bb(const bf* __restrict__ Qvh, const bf* __restrict__ Qvl,
                   const bf* __restrict__ Rh, const bf* __restrict__ Rl,
                   float* __restrict__ C2)
{
    const int bh = blockIdx.z, b = bh >> 4, h = bh & 15;
    const int i0 = blockIdx.y * 64, n0 = blockIdx.x * 64;
    if (n0 + i0 < 385) return;

    __shared__ bf sQh[64][72], sQl[64][72], sRh[64][72], sRl[64][72];

    const int tid = threadIdx.x, lane = tid & 31, wid = tid >> 5;
    const int wm = wid >> 1, wn = wid & 1;

    {
        const int row = tid >> 1, cb = (tid & 1) * 32;
        const size_t qoff = (size_t)((i0 + row) * BS + b) * DIMM + h * HD + cb;
        const size_t roff = (size_t)(n0 + row) * DIMM + h * HD + cb;
        #pragma unroll
        for (int q = 0; q < 4; q++) {
            *(uint4*)&sQh[row][cb + q * 8] = *(const uint4*)&Qvh[qoff + q * 8];
            *(uint4*)&sQl[row][cb + q * 8] = *(const uint4*)&Qvl[qoff + q * 8];
            *(uint4*)&sRh[row][cb + q * 8] = *(const uint4*)&Rh[roff + q * 8];
            *(uint4*)&sRl[row][cb + q * 8] = *(const uint4*)&Rl[roff + q * 8];
        }
    }
    __syncthreads();

    float acc[2][4][4] = {};
    #pragma unroll
    for (int s = 0; s < 4; s++) {
        const int ks = s * 16;
        uint32_t ah[2][4], al[2][4], bh2[4][2], bl2[4][2];
        #pragma unroll
        for (int f = 0; f < 2; f++) {
            int row = wm * 32 + f * 16 + (lane & 15);
            int kc  = ks + ((lane & 16) >> 1);
            ldsm4(ah[f], smem_u32(&sQh[row][kc]));
            ldsm4(al[f], smem_u32(&sQl[row][kc]));
        }
        #pragma unroll
        for (int g4 = 0; g4 < 2; g4++) {
            int nrow = wn * 32 + g4 * 16 + (lane & 15);
            int kc   = ks + ((lane & 16) >> 1);
            uint32_t t[4];
            ldsm4(t, smem_u32(&sRh[nrow][kc]));
            bh2[2*g4][0] = t[0]; bh2[2*g4+1][0] = t[1];
            bh2[2*g4][1] = t[2]; bh2[2*g4+1][1] = t[3];
            ldsm4(t, smem_u32(&sRl[nrow][kc]));
            bl2[2*g4][0] = t[0]; bl2[2*g4+1][0] = t[1];
            bl2[2*g4][1] = t[2]; bl2[2*g4+1][1] = t[3];
        }
        #pragma unroll
        for (int f = 0; f < 2; f++)
            #pragma unroll
            for (int g = 0; g < 4; g++) {
                mmabf(acc[f][g], ah[f], bh2[g]);
                mmabf(acc[f][g], ah[f], bl2[g]);
                mmabf(acc[f][g], al[f], bh2[g]);
            }
    }

    const int r = lane >> 2, c2 = (lane & 3) * 2;
    float* out = C2 + (size_t)bh * CUR * FULL;
    #pragma unroll
    for (int f = 0; f < 2; f++) {
        int row0 = i0 + wm * 32 + f * 16 + r;
        #pragma unroll
        for (int g = 0; g < 4; g++) {
            int col = n0 + wn * 32 + g * 8 + c2;
            *(float2*)&out[(size_t)row0 * FULL + col]       = make_float2(acc[f][g][0], acc[f][g][1]);
            *(float2*)&out[(size_t)(row0 + 8) * FULL + col] = make_float2(acc[f][g][2], acc[f][g][3]);
        }
    }
}

// ---------------------------------------------------------------------------
// Fused attention: 128 query rows / block, 256 threads, __launch_bounds(256,2)
// to force 2 blocks/SM (16 warps/SM). 2-stage cp.async K/V pipeline.
// ---------------------------------------------------------------------------
#define ASTAGE 36864
__global__ __launch_bounds__(256, 2)
void attn_ca(const bf* __restrict__ Quh, const bf* __restrict__ Qul,
             const bf* __restrict__ KVh, const bf* __restrict__ KVl,
             const float* __restrict__ C2,
             bf* __restrict__ AVh, bf* __restrict__ AVl)
{
    extern __shared__ char dsm[];
    __shared__ bf Qh_s[128][72], Ql_s[128][72];

    const int bh = blockIdx.y, b = bh >> 4, h = bh & 15;
    const int i0 = blockIdx.x * 128;

    const int tid = threadIdx.x, lane = tid & 31, w = tid >> 5;
    const int r = lane >> 2, cq = lane & 3;

    const int jtiles = i0 / 64 + 10;

    const int kii = tid >> 2, kcb = (tid & 3) * 16;
    auto issue_kv = [&](int jt) {
        char* st = dsm + (jt & 1) * ASTAGE;
        const size_t koff = (size_t)((jt * 64 + kii) * BS + b) * (2 * DIMM) + h * HD + kcb;
        const char* gKh = (const char*)(KVh + koff);
        const char* gKl = (const char*)(KVl + koff);
        const char* gVh = (const char*)(KVh + koff + DIMM);
        const char* gVl = (const char*)(KVl + koff + DIMM);
        const uint32_t d = smem_u32(st) + kii * 144 + (tid & 3) * 32;
        #pragma unroll
        for (int c = 0; c < 2; c++) {
            CPA(d +         c * 16, gKh + c * 16);
            CPA(d + 9216  + c * 16, gKl + c * 16);
            CPA(d + 18432 + c * 16, gVh + c * 16);
            CPA(d + 27648 + c * 16, gVl + c * 16);
        }
        CPC();
    };

    issue_kv(0);
    {
        const int qi = tid >> 1, qc = (tid & 1) * 32;
        const size_t qoff = (size_t)((i0 + qi) * BS + b) * DIMM + h * HD + qc;
        #pragma unroll
        for (int q = 0; q < 4; q++) {
            *(uint4*)&Qh_s[qi][qc + q * 8] = *(const uint4*)&Quh[qoff + q * 8];
            *(uint4*)&Ql_s[qi][qc + q * 8] = *(const uint4*)&Qul[qoff + q * 8];
        }
    }
    __syncthreads();

    uint32_t qh[4][4], ql[4][4];
    #pragma unroll
    for (int s = 0; s < 4; s++) {
        int rowi = w * 16 + (lane & 15);
        int kc  = s * 16 + ((lane & 16) >> 1);
        ldsm4(qh[s], smem_u32(&Qh_s[rowi][kc]));
        ldsm4(ql[s], smem_u32(&Ql_s[rowi][kc]));
    }

    float oacc[8][4] = {};
    float m0 = -1e30f, m1 = -1e30f, l0 = 0.f, l1 = 0.f;

    const int irow0 = i0 + w * 16 + r;
    const float* c2row0 = C2 + ((size_t)bh * CUR + irow0) * FULL;
    const float* c2row1 = c2row0 + (size_t)8 * FULL;

    for (int jt = 0; jt < jtiles; jt++) {
        const int j0 = jt * 64;
        CPW(0);
        __syncthreads();
        if (jt + 1 < jtiles) issue_kv(jt + 1);

        char* st = dsm + (jt & 1) * ASTAGE;
        bf* Kh_s = (bf*)st;
        bf* Kl_s = (bf*)(st + 9216);
        bf* Vh_s = (bf*)(st + 18432);
        bf* Vl_s = (bf*)(st + 27648);

        float sacc[8][4] = {};
        #pragma unroll
        for (int s = 0; s < 4; s++) {
            const int ks = s * 16;
            uint32_t bhf[8][2], blf[8][2];
            #pragma unroll
            for (int g4 = 0; g4 < 4; g4++) {
                int nrow = g4 * 16 + (lane & 15);
                int kc   = ks + ((lane & 16) >> 1);
                uint32_t t[4];
                ldsm4(t, smem_u32(&Kh_s[nrow * 72 + kc]));
                bhf[2*g4][0] = t[0]; bhf[2*g4+1][0] = t[1];
                bhf[2*g4][1] = t[2]; bhf[2*g4+1][1] = t[3];
                ldsm4(t, smem_u32(&Kl_s[nrow * 72 + kc]));
                blf[2*g4][0] = t[0]; blf[2*g4+1][0] = t[1];
                blf[2*g4][1] = t[2]; blf[2*g4+1][1] = t[3];
            }
            #pragma unroll
            for (int g = 0; g < 8; g++) {
                mmabf(sacc[g], qh[s], bhf[g]);
                mmabf(sacc[g], qh[s], blf[g]);
                mmabf(sacc[g], ql[s], bhf[g]);
            }
        }

        const bool need_mask = (j0 + 63 > irow0 + PREV);
        #pragma unroll
        for (int g = 0; g < 8; g++) {
            int jg  = j0 + g * 8 + 2 * cq;
            int k00 = jg - irow0 + 511;
            int k10 = k00 - 8;
            if (!need_mask) {
                sacc[g][0] += c2row0[k00];
                sacc[g][1] += c2row0[k00 + 1];
                sacc[g][2] += c2row1[k10];
                sacc[g][3] += c2row1[k10 + 1];
            } else {
                sacc[g][0] = (k00     <= 1023) ? sacc[g][0] + c2row0[k00]     : -1e30f;
                sacc[g][1] = (k00 + 1 <= 1023) ? sacc[g][1] + c2row0[k00 + 1] : -1e30f;
                sacc[g][2] = (k10     <= 1023) ? sacc[g][2] + c2row1[k10]     : -1e30f;
                sacc[g][3] = (k10 + 1 <= 1023) ? sacc[g][3] + c2row1[k10 + 1] : -1e30f;
            }
        }

        float mx0 = -1e30f, mx1 = -1e30f;
        #pragma unroll
        for (int g = 0; g < 8; g++) {
            mx0 = fmaxf(mx0, fmaxf(sacc[g][0], sacc[g][1]));
            mx1 = fmaxf(mx1, fmaxf(sacc[g][2], sacc[g][3]));
        }
        mx0 = fmaxf(mx0, __shfl_xor_sync(0xffffffffu, mx0, 1));
        mx0 = fmaxf(mx0, __shfl_xor_sync(0xffffffffu, mx0, 2));
        mx1 = fmaxf(mx1, __shfl_xor_sync(0xffffffffu, mx1, 1));
        mx1 = fmaxf(mx1, __shfl_xor_sync(0xffffffffu, mx1, 2));

        float mn0 = fmaxf(m0, mx0), mn1 = fmaxf(m1, mx1);
        float a0 = __expf(m0 - mn0), a1 = __expf(m1 - mn1);
        m0 = mn0; m1 = mn1;
        l0 *= a0; l1 *= a1;
        #pragma unroll
        for (int g = 0; g < 8; g++) {
            oacc[g][0] *= a0; oacc[g][1] *= a0;
            oacc[g][2] *= a1; oacc[g][3] *= a1;
        }

        // exp + immediate bf16 split (keeps p out of live fp32 registers)
        uint32_t pah[4][4], pal[4][4];
        #pragma unroll
        for (int t4 = 0; t4 < 4; t4++) {
            #pragma unroll
            for (int gg = 0; gg < 2; gg++) {
                int g = 2 * t4 + gg;
                float p0 = __expf(sacc[g][0] - m0);
                float p1 = __expf(sacc[g][1] - m0);
                float p2 = __expf(sacc[g][2] - m1);
                float p3 = __expf(sacc[g][3] - m1);
                l0 += p0 + p1;
                l1 += p2 + p3;
                split2(p0, p1, pah[t4][2*gg],     pal[t4][2*gg]);
                split2(p2, p3, pah[t4][2*gg + 1], pal[t4][2*gg + 1]);
            }
        }

        #pragma unroll
        for (int t4 = 0; t4 < 4; t4++) {
            uint32_t vhf[8][2], vlf[8][2];
            #pragma unroll
            for (int g4 = 0; g4 < 4; g4++) {
                int krow = t4 * 16 + (lane & 15);
                int ncc  = g4 * 16 + ((lane & 16) >> 1);
                uint32_t t[4];
                ldsm4t(t, smem_u32(&Vh_s[krow * 72 + ncc]));
                vhf[2*g4][0] = t[0]; vhf[2*g4][1] = t[1];
                vhf[2*g4+1][0] = t[2]; vhf[2*g4+1][1] = t[3];
                ldsm4t(t, smem_u32(&Vl_s[krow * 72 + ncc]));
                vlf[2*g4][0] = t[0]; vlf[2*g4][1] = t[1];
                vlf[2*g4+1][0] = t[2]; vlf[2*g4+1][1] = t[3];
            }
            #pragma unroll
            for (int g = 0; g < 8; g++) {
                mmabf(oacc[g], pah[t4], vhf[g]);
                mmabf(oacc[g], pah[t4], vlf[g]);
                mmabf(oacc[g], pal[t4], vhf[g]);
            }
        }
    }

    l0 += __shfl_xor_sync(0xffffffffu, l0, 1);
    l0 += __shfl_xor_sync(0xffffffffu, l0, 2);
    l1 += __shfl_xor_sync(0xffffffffu, l1, 1);
    l1 += __shfl_xor_sync(0xffffffffu, l1, 2);
    const float inv0 = 1.f / l0, inv1 = 1.f / l1;

    const size_t o0 = (size_t)(irow0 * BS + b) * DIMM + h * HD;
    const size_t o1 = (size_t)((irow0 + 8) * BS + b) * DIMM + h * HD;
    #pragma unroll
    for (int g = 0; g < 8; g++) {
        int col = g * 8 + 2 * cq;
        store_split(&AVh[o0 + col], &AVl[o0 + col], oacc[g][0] * inv0, oacc[g][1] * inv0);
        store_split(&AVh[o1 + col], &AVl[o1 + col], oacc[g][2] * inv1, oacc[g][3] * inv1);
    }
}

// ---------------------------------------------------------------------------
// Launch
// ---------------------------------------------------------------------------
extern "C" void kernel_launch(void* const* d_in, const int* in_sizes, int n_in,
                              void* d_out, int out_size)
{
    const float* inputs  = (const float*)d_in[0];
    const float* pos_emb = (const float*)d_in[1];
    const float* full_in = (const float*)d_in[2];
    const float* u       = (const float*)d_in[3];
    const float* v       = (const float*)d_in[4];
    const float* W_kv    = (const float*)d_in[5];
    const float* b_kv    = (const float*)d_in[6];
    const float* W_q     = (const float*)d_in[7];
    const float* b_q     = (const float*)d_in[8];
    const float* W_pos   = (const float*)d_in[9];
    const float* b_pos   = (const float*)d_in[10];
    const float* W_proj  = (const float*)d_in[11];
    const float* b_proj  = (const float*)d_in[12];
    float* out = (float*)d_out;

    bf *FIh, *FIl, *INh, *INl, *PEh, *PEl, *Wkvh, *Wkvl, *Wqh, *Wql,
       *Wph, *Wpl, *Wprh, *Wprl, *KVh, *KVl, *Quh, *Qul, *Qvh, *Qvl,
       *Rh, *Rl, *AVh, *AVl;
    float *C2;
    cudaGetSymbolAddress((void**)&FIh, g_FIh);   cudaGetSymbolAddress((void**)&FIl, g_FIl);
    cudaGetSymbolAddress((void**)&INh, g_INh);   cudaGetSymbolAddress((void**)&INl, g_INl);
    cudaGetSymbolAddress((void**)&PEh, g_PEh);   cudaGetSymbolAddress((void**)&PEl, g_PEl);
    cudaGetSymbolAddress((void**)&Wkvh, g_Wkvh); cudaGetSymbolAddress((void**)&Wkvl, g_Wkvl);
    cudaGetSymbolAddress((void**)&Wqh, g_Wqh);   cudaGetSymbolAddress((void**)&Wql, g_Wql);
    cudaGetSymbolAddress((void**)&Wph, g_Wph);   cudaGetSymbolAddress((void**)&Wpl, g_Wpl);
    cudaGetSymbolAddress((void**)&Wprh, g_Wprh); cudaGetSymbolAddress((void**)&Wprl, g_Wprl);
    cudaGetSymbolAddress((void**)&KVh, g_KVh);   cudaGetSymbolAddress((void**)&KVl, g_KVl);
    cudaGetSymbolAddress((void**)&Quh, g_Quh);   cudaGetSymbolAddress((void**)&Qul, g_Qul);
    cudaGetSymbolAddress((void**)&Qvh, g_Qvh);   cudaGetSymbolAddress((void**)&Qvl, g_Qvl);
    cudaGetSymbolAddress((void**)&Rh, g_Rh);     cudaGetSymbolAddress((void**)&Rl, g_Rl);
    cudaGetSymbolAddress((void**)&AVh, g_AVh);   cudaGetSymbolAddress((void**)&AVl, g_AVl);
    cudaGetSymbolAddress((void**)&C2, g_C2);

    const int GSM = 4 * GSTAGE;     // 151552
    const int ASM = 2 * ASTAGE;     // 73728
    cudaFuncSetAttribute(gemm_mega, cudaFuncAttributeMaxDynamicSharedMemorySize, GSM);
    cudaFuncSetAttribute(attn_ca,   cudaFuncAttributeMaxDynamicSharedMemorySize, ASM);

    // 1. All conversions in one grid
    CT ct;
    ct.s[0] = full_in; ct.h[0] = FIh;  ct.l[0] = FIl;
    ct.s[1] = inputs;  ct.h[1] = INh;  ct.l[1] = INl;
    ct.s[2] = pos_emb; ct.h[2] = PEh;  ct.l[2] = PEl;
    ct.s[3] = W_kv;    ct.h[3] = Wkvh; ct.l[3] = Wkvl;
    ct.s[4] = W_q;     ct.h[4] = Wqh;  ct.l[4] = Wql;
    ct.s[5] = W_pos;   ct.h[5] = Wph;  ct.l[5] = Wpl;
    ct.s[6] = W_proj;  ct.h[6] = Wprh; ct.l[6] = Wprl;
    ct.end[0] = 4096;  ct.end[1] = 6144;  ct.end[2] = 7168;
    ct.end[3] = 9216;  ct.end[4] = 10240; ct.end[5] = 11264; ct.end[6] = 12288;
    cvt_mega<<<12288, 256>>>(ct);

    // 2. Mega GEMM {KV, Q(+u/v, x0.125), R}
    GT3 ts;
    ts.t[0] = { FIh, FIl, Wkvh, Wkvl, b_kv, nullptr, nullptr,
                nullptr, KVh, KVl, nullptr, nullptr, 2048, 1024, 16, 1 };
    ts.t[1] = { INh, INl, Wqh, Wql, b_q, u, v,
                nullptr, Quh, Qul, Qvh, Qvl, 1024, 1024, 8, 2 };
    ts.t[2] = { PEh, PEl, Wph, Wpl, b_pos, nullptr, nullptr,
                nullptr, Rh, Rl, nullptr, nullptr, 1024, 1024, 8, 1 };
    ts.end0 = 512; ts.end1 = 640;
    gemm_mega<<<704, 256, GSM>>>(ts);

    // 3. Position scores (pre-scaled)
    pos_scores_bb<<<dim3(FULL / 64, CUR / 64, BS * NH), 128>>>(Qvh, Qvl, Rh, Rl, C2);

    // 4. Fused attention (128 rows/block, 2 blocks/SM)
    attn_ca<<<dim3(CUR / 128, BS * NH), 256, ASM>>>(Quh, Qul, KVh, KVl, C2, AVh, AVl);

    // 5. out = AV @ W_proj + b_proj (fp32)
    GT3 tp;
    tp.t[0] = { AVh, AVl, Wprh, Wprl, b_proj, nullptr, nullptr,
                out, nullptr, nullptr, nullptr, nullptr, 1024, 1024, 8, 0 };
    tp.t[1] = tp.t[0]; tp.t[2] = tp.t[0];
    tp.end0 = 128; tp.end1 = 128;
    gemm_mega<<<128, 256, GSM>>>(tp);
}